// round 10
// baseline (speedup 1.0000x reference)
#include <cuda_runtime.h>
#include <cuda_bf16.h>
#include <math.h>
#include <stdint.h>

#define B_   4
#define L_   4096
#define D_   1024
#define H_   16
#define DK_  64
#define BH_  (B_ * H_)
#define TOPK 8
#define M_   (B_ * L_)   // 16384

// ---------------- scratch (device globals; no runtime allocation) ----------
__device__ float g_Vp[M_ * D_];
__device__ float g_pre[M_ * D_];
__device__ float g_Wvr[D_ * D_];        // pre-rounded+permuted Wv
__device__ float g_Wor[D_ * D_];        // pre-rounded+permuted Wo
__device__ float g_qm[BH_ * L_];
__device__ float g_km[BH_ * L_];
__device__ float g_Wm[2 * H_ * D_];
__device__ float g_w[BH_ * TOPK];
__device__ int   g_delays[BH_ * TOPK];

// ---------------- helpers ----------------------------------------------------
__device__ __forceinline__ uint32_t smem_u32(const void* p) {
    uint32_t a;
    asm("{ .reg .u64 t; cvta.to.shared.u64 t, %1; cvt.u32.u64 %0, t; }"
        : "=r"(a) : "l"(p));
    return a;
}
__device__ __forceinline__ void cp16(uint32_t dst, const void* src) {
    asm volatile("cp.async.cg.shared.global [%0], [%1], 16;"
                 :: "r"(dst), "l"(src));
}
__device__ __forceinline__ uint32_t f2tf32(float f) {
    uint32_t u;
    asm("cvt.rna.tf32.f32 %0, %1;" : "=r"(u) : "f"(f));
    return u;
}
__device__ __forceinline__ void mma_tf32(float* d, const uint32_t* a, const uint32_t* b) {
    asm volatile(
        "mma.sync.aligned.m16n8k8.row.col.f32.tf32.tf32.f32 "
        "{%0,%1,%2,%3}, {%4,%5,%6,%7}, {%8,%9}, {%0,%1,%2,%3};"
        : "+f"(d[0]), "+f"(d[1]), "+f"(d[2]), "+f"(d[3])
        : "r"(a[0]), "r"(a[1]), "r"(a[2]), "r"(a[3]), "r"(b[0]), "r"(b[1]));
}

// ---------------- W prep: tf32-round + intra-64 column permutation ----------
__global__ __launch_bounds__(256) void wprep_kernel(
    const float* __restrict__ W, float* __restrict__ Wr)
{
    int id = blockIdx.x * 256 + threadIdx.x;
    int k = id >> 10;
    int c = id & 1023;
    int g = c & ~63;
    int p = c & 63;
    int v = ((p & 7) << 3) + (p >> 3);
    float x = __ldg(&W[(size_t)k * 1024 + g + v]);
    Wr[id] = __uint_as_float(f2tf32(x));
}

// ---------------- tf32 mma GEMM: block 128x256, warp tile 64x64 --------------
#define A_ST_F 4096              // 128 rows x 32 k (floats)
#define B_ST_F 8192              // 32 k x 256 n
#define STAGE_F 12288
#define STAGE_BYTES (STAGE_F * 4)       // 48 KB
#define GEMM_SMEM (3 * STAGE_BYTES)     // 144 KB

template<bool CVT_A>
__global__ __launch_bounds__(256, 1) void gemm_tf32_kernel(
    const float* __restrict__ A, const float* __restrict__ W,
    const float* __restrict__ bias, float* __restrict__ C)
{
    extern __shared__ float sm[];
    const uint32_t su = smem_u32(sm);
    const int tid = threadIdx.x;
    const int bn = blockIdx.x;          // 0..3 (256-col tiles)
    const int bm = blockIdx.y;          // 0..127 (128-row tiles)
    const int wid = tid >> 5, lane = tid & 31;
    const int wm = wid >> 2, wn = wid & 3;   // 2 x 4 warps, 64x64 tiles
    const int qr = lane >> 2, qc = lane & 3;

    // global load bases
    const float* Ab = A + (size_t)(bm * 128 + (tid >> 3)) * 1024 + (tid & 7) * 4;
    const float* Wb = W + (size_t)(tid >> 6) * 1024 + bn * 256 + (tid & 63) * 4;

    // smem byte offsets, swizzled
    uint32_t saoff[4], sboff[8];
    #pragma unroll
    for (int p = 0; p < 4; p++) {
        int row = (tid >> 3) + p * 32;
        saoff[p] = (row * 32 + (((tid & 7) ^ (row & 7)) << 2)) * 4;
    }
    #pragma unroll
    for (int p = 0; p < 8; p++) {
        int k = (tid >> 6) + p * 4;
        sboff[p] = (A_ST_F + k * 256 + (((tid & 63) << 2) ^ ((k & 3) << 3))) * 4;
    }

    float acc[4][8][4];
    #pragma unroll
    for (int mb = 0; mb < 4; mb++)
        #pragma unroll
        for (int j = 0; j < 8; j++)
            #pragma unroll
            for (int v = 0; v < 4; v++) acc[mb][j][v] = 0.0f;

    auto load_stage = [&](int st, int kt) {
        uint32_t base = su + st * STAGE_BYTES;
        #pragma unroll
        for (int p = 0; p < 4; p++)
            cp16(base + saoff[p], Ab + kt * 32 + p * 32 * 1024);
        #pragma unroll
        for (int p = 0; p < 8; p++)
            cp16(base + sboff[p], Wb + (size_t)(kt * 32 + p * 4) * 1024);
    };

    load_stage(0, 0);
    asm volatile("cp.async.commit_group;");
    load_stage(1, 1);
    asm volatile("cp.async.commit_group;");

    const int rowa0 = wm * 64 + qr;
    const int colb = (wn * 64 + qr * 8) ^ (qc << 3);

    for (int kt = 0; kt < 32; kt++) {
        const int st = kt % 3;
        if (kt < 30) asm volatile("cp.async.wait_group 1;");
        else         asm volatile("cp.async.wait_group 0;");
        __syncthreads();
        if (kt < 30) {
            load_stage((kt + 2) % 3, kt + 2);
            asm volatile("cp.async.commit_group;");
        }

        const float* As = sm + st * STAGE_F;
        const float* Bs = As + A_ST_F;

        #pragma unroll
        for (int s = 0; s < 4; s++) {
            uint32_t afr[4][4];
            #pragma unroll
            for (int mb = 0; mb < 4; mb++) {
                int row = rowa0 + mb * 16;
                int s0 = (((s * 2)     ^ qr) << 2) + qc;
                int s1 = (((s * 2 + 1) ^ qr) << 2) + qc;
                if (CVT_A) {
                    afr[mb][0] = f2tf32(As[row * 32 + s0]);
                    afr[mb][1] = f2tf32(As[(row + 8) * 32 + s0]);
                    afr[mb][2] = f2tf32(As[row * 32 + s1]);
                    afr[mb][3] = f2tf32(As[(row + 8) * 32 + s1]);
                } else {
                    afr[mb][0] = __float_as_uint(As[row * 32 + s0]);
                    afr[mb][1] = __float_as_uint(As[(row + 8) * 32 + s0]);
                    afr[mb][2] = __float_as_uint(As[row * 32 + s1]);
                    afr[mb][3] = __float_as_uint(As[(row + 8) * 32 + s1]);
                }
            }
            const float4* br0 = (const float4*)&Bs[(s * 8 + qc) * 256 + colb];
            const float4* br1 = (const float4*)&Bs[(s * 8 + qc + 4) * 256 + colb];
            float4 b00 = br0[0], b01 = br0[1];
            float4 b10 = br1[0], b11 = br1[1];
            uint32_t bfr[8][2];
            bfr[0][0] = __float_as_uint(b00.x); bfr[0][1] = __float_as_uint(b10.x);
            bfr[1][0] = __float_as_uint(b00.y); bfr[1][1] = __float_as_uint(b10.y);
            bfr[2][0] = __float_as_uint(b00.z); bfr[2][1] = __float_as_uint(b10.z);
            bfr[3][0] = __float_as_uint(b00.w); bfr[3][1] = __float_as_uint(b10.w);
            bfr[4][0] = __float_as_uint(b01.x); bfr[4][1] = __float_as_uint(b11.x);
            bfr[5][0] = __float_as_uint(b01.y); bfr[5][1] = __float_as_uint(b11.y);
            bfr[6][0] = __float_as_uint(b01.z); bfr[6][1] = __float_as_uint(b11.z);
            bfr[7][0] = __float_as_uint(b01.w); bfr[7][1] = __float_as_uint(b11.w);

            #pragma unroll
            for (int mb = 0; mb < 4; mb++)
                #pragma unroll
                for (int j = 0; j < 8; j++)
                    mma_tf32(acc[mb][j], afr[mb], bfr[j]);
        }
    }

    #pragma unroll
    for (int mb = 0; mb < 4; mb++) {
        int row = bm * 128 + wm * 64 + mb * 16 + qr;
        #pragma unroll
        for (int j = 0; j < 8; j++) {
            int col = bn * 256 + wn * 64 + j * 8 + qc * 2;
            float2 bb = *(const float2*)(bias + col);
            float2 o0 = make_float2(acc[mb][j][0] + bb.x, acc[mb][j][1] + bb.y);
            float2 o1 = make_float2(acc[mb][j][2] + bb.x, acc[mb][j][3] + bb.y);
            *(float2*)(C + (size_t)row * 1024 + col)       = o0;
            *(float2*)(C + (size_t)(row + 8) * 1024 + col) = o1;
        }
    }
}

// ---------------- mean-reduced weights --------------------------------------
__global__ __launch_bounds__(256) void wmean_kernel(
    const float* __restrict__ Wq, const float* __restrict__ Wk,
    float* __restrict__ Wm)
{
    int id = blockIdx.x * 256 + threadIdx.x;
    int t = id >> 14;
    int h = (id >> 10) & 15;
    int d = id & 1023;
    const float* W = t ? Wk : Wq;
    const float4* p = (const float4*)(W + (size_t)d * 1024 + h * 64);
    float s = 0.0f;
    #pragma unroll
    for (int c = 0; c < 16; c++) {
        float4 v = __ldg(&p[c]);
        s += (v.x + v.y) + (v.z + v.w);
    }
    Wm[id] = s * (1.0f / 64.0f);
}

// ---------------- skinny mean-projection ------------------------------------
__global__ __launch_bounds__(256) void qkmean_kernel(
    const float* __restrict__ queries, const float* __restrict__ keys,
    const float* __restrict__ Wm, float* __restrict__ qm, float* __restrict__ km)
{
    extern __shared__ float swm[];
    const int tid = threadIdx.x;
    for (int i = tid * 4; i < 32768; i += 1024)
        *(float4*)(swm + i) = *(const float4*)(Wm + i);
    __syncthreads();

    const int w = tid >> 5, lane = tid & 31;
    const int m0 = blockIdx.x * 32 + w * 4;

    #pragma unroll
    for (int ph = 0; ph < 2; ph++) {
        const float* src = ph ? keys : queries;
        float* dst = ph ? g_km : g_qm;
        const float* base = src + (size_t)m0 * 1024 + lane * 4;
        const float* tw_ = swm + ph * 16384 + lane * 4;

        float acc[4][16];
        #pragma unroll
        for (int r = 0; r < 4; r++)
            #pragma unroll
            for (int h = 0; h < 16; h++) acc[r][h] = 0.0f;

        #pragma unroll
        for (int c = 0; c < 8; c++) {
            float4 x0 = *(const float4*)(base + 0 * 1024 + c * 128);
            float4 x1 = *(const float4*)(base + 1 * 1024 + c * 128);
            float4 x2 = *(const float4*)(base + 2 * 1024 + c * 128);
            float4 x3 = *(const float4*)(base + 3 * 1024 + c * 128);
            #pragma unroll
            for (int h = 0; h < 16; h++) {
                float4 wv = *(const float4*)(tw_ + h * 1024 + c * 128);
                acc[0][h] += x0.x*wv.x + x0.y*wv.y + x0.z*wv.z + x0.w*wv.w;
                acc[1][h] += x1.x*wv.x + x1.y*wv.y + x1.z*wv.z + x1.w*wv.w;
                acc[2][h] += x2.x*wv.x + x2.y*wv.y + x2.z*wv.z + x2.w*wv.w;
                acc[3][h] += x3.x*wv.x + x3.y*wv.y + x3.z*wv.z + x3.w*wv.w;
            }
        }

        #pragma unroll
        for (int r = 0; r < 4; r++) {
            int m = m0 + r;
            int b = m >> 12, l = m & 4095;
            float* out = dst + (((size_t)b * 16) << 12) + l;
            #pragma unroll
            for (int h = 0; h < 16; h++) {
                float v = acc[r][h];
                v += __shfl_xor_sync(0xFFFFFFFFu, v, 16);
                v += __shfl_xor_sync(0xFFFFFFFFu, v, 8);
                v += __shfl_xor_sync(0xFFFFFFFFu, v, 4);
                v += __shfl_xor_sync(0xFFFFFFFFu, v, 2);
                v += __shfl_xor_sync(0xFFFFFFFFu, v, 1);
                if (lane == h) out[(size_t)h << 12] = v;
            }
        }
    }
}

// ---------------- FFT correlation + top-8 + softmax (fused, 512 thr) --------
__global__ __launch_bounds__(512) void fft_corr_top8_kernel(
    const float* __restrict__ qm, const float* __restrict__ km,
    float* __restrict__ w, int* __restrict__ delays)
{
    extern __shared__ float2 fsm[];
    float2* buf0 = fsm;
    float2* buf1 = fsm + 4096;
    float2* tw   = fsm + 8192;
    float*  sc   = (float*)(fsm + 8192);
    __shared__ float svals[512];
    __shared__ int   sidx[512];
    __shared__ float topv[TOPK];
    __shared__ int   topi[TOPK];

    const int bh = blockIdx.x, tid = threadIdx.x;
    const float* q = qm + (size_t)bh * L_;
    const float* k = km + (size_t)bh * L_;
    for (int i = tid; i < 4096; i += 512) buf0[i] = make_float2(q[i], k[i]);
    for (int r = tid; r < 2048; r += 512) {
        float sv, cv;
        __sincosf(-6.2831853071795865f * (float)r / 4096.0f, &sv, &cv);
        tw[r] = make_float2(cv, sv);
    }
    __syncthreads();

    // FFT #1
    {
        float2 *x = buf0, *y = buf1;
        for (int t = 0; t < 12; t++) {
            int s = 1 << t;
            #pragma unroll
            for (int ii = 0; ii < 4; ii++) {
                int idx = tid + ii * 512;
                float2 a = x[idx];
                float2 b = x[idx + 2048];
                int r = idx & ~(s - 1);
                int kl = idx & (s - 1);
                float2 wv = tw[r];
                float dx = a.x - b.x, dy = a.y - b.y;
                y[2 * r + kl]     = make_float2(a.x + b.x, a.y + b.y);
                y[2 * r + kl + s] = make_float2(dx * wv.x - dy * wv.y,
                                                dx * wv.y + dy * wv.x);
            }
            __syncthreads();
            float2* t2 = x; x = y; y = t2;
        }
    }

    // Hermitian split + conj(Q*conj(K)) into buf1
    for (int i = tid; i < 4096; i += 512) {
        float2 zi = buf0[i];
        float2 zn = buf0[(4096 - i) & 4095];
        float qx = 0.5f * (zi.x + zn.x);
        float qy = 0.5f * (zi.y - zn.y);
        float ux = zi.x - zn.x;
        float uy = zi.y + zn.y;
        float kx = 0.5f * uy;
        float ky = -0.5f * ux;
        float px = qx * kx + qy * ky;
        float py = qy * kx - qx * ky;
        buf1[i] = make_float2(px, -py);
    }
    __syncthreads();

    // FFT #2
    {
        float2 *x = buf1, *y = buf0;
        for (int t = 0; t < 12; t++) {
            int s = 1 << t;
            #pragma unroll
            for (int ii = 0; ii < 4; ii++) {
                int idx = tid + ii * 512;
                float2 a = x[idx];
                float2 b = x[idx + 2048];
                int r = idx & ~(s - 1);
                int kl = idx & (s - 1);
                float2 wv = tw[r];
                float dx = a.x - b.x, dy = a.y - b.y;
                y[2 * r + kl]     = make_float2(a.x + b.x, a.y + b.y);
                y[2 * r + kl + s] = make_float2(dx * wv.x - dy * wv.y,
                                                dx * wv.y + dy * wv.x);
            }
            __syncthreads();
            float2* t2 = x; x = y; y = t2;
        }
    }

    for (int i = tid; i < 4096; i += 512)
        sc[i] = buf1[i].x * (1.0f / 4096.0f);
    __syncthreads();

    for (int r = 0; r < TOPK; r++) {
        float best = -INFINITY; int bi = 0;
        for (int i = tid; i < 4096; i += 512) {
            float v = sc[i];
            if (v > best) { best = v; bi = i; }
        }
        svals[tid] = best;
        sidx[tid] = bi;
        __syncthreads();
        for (int s = 256; s > 0; s >>= 1) {
            if (tid < s) {
                float v2 = svals[tid + s];
                int   i2 = sidx[tid + s];
                float v1 = svals[tid];
                int   i1 = sidx[tid];
                if (v2 > v1 || (v2 == v1 && i2 < i1)) {
                    svals[tid] = v2;
                    sidx[tid] = i2;
                }
            }
            __syncthreads();
        }
        if (tid == 0) {
            topv[r] = svals[0];
            topi[r] = sidx[0];
            sc[sidx[0]] = -INFINITY;
        }
        __syncthreads();
    }

    if (tid == 0) {
        float mx = topv[0];
        float e[TOPK], s = 0.0f;
        #pragma unroll
        for (int r = 0; r < TOPK; r++) { e[r] = expf(topv[r] - mx); s += e[r]; }
        float inv = 1.0f / s;
        #pragma unroll
        for (int r = 0; r < TOPK; r++) {
            w[bh * TOPK + r] = e[r] * inv;
            delays[bh * TOPK + r] = topi[r];
        }
    }
}

// ---------------- gather (writes tf32-rounded output) ------------------------
__global__ __launch_bounds__(256) void gather_kernel(
    const float* __restrict__ Vp, const float* __restrict__ w,
    const int* __restrict__ delays, float* __restrict__ out)
{
    unsigned gid = blockIdx.x * blockDim.x + threadIdx.x;
    int d4 = gid & 255;
    int l  = (gid >> 8) & (L_ - 1);
    int b  = gid >> 20;
    int h  = d4 >> 4;
    int bh = b * H_ + h;

    float4 a = make_float4(0.f, 0.f, 0.f, 0.f);
    #pragma unroll
    for (int r = 0; r < TOPK; r++) {
        float wr = __ldg(&w[bh * TOPK + r]);
        int   dl = __ldg(&delays[bh * TOPK + r]);
        int   lm = (l - dl) & (L_ - 1);
        const float4 v = *(const float4*)(Vp + (size_t)(b * L_ + lm) * D_ + d4 * 4);
        a.x += wr * v.x; a.y += wr * v.y; a.z += wr * v.z; a.w += wr * v.w;
    }
    float4 o;
    o.x = __uint_as_float(f2tf32(a.x));
    o.y = __uint_as_float(f2tf32(a.y));
    o.z = __uint_as_float(f2tf32(a.z));
    o.w = __uint_as_float(f2tf32(a.w));
    *(float4*)(out + (size_t)gid * 4) = o;
}

// ---------------- launch ------------------------------------------------------
extern "C" void kernel_launch(void* const* d_in, const int* in_sizes, int n_in,
                              void* d_out, int out_size)
{
    const float* queries = (const float*)d_in[0];
    const float* keys    = (const float*)d_in[1];
    const float* values  = (const float*)d_in[2];
    const float* Wq = (const float*)d_in[3];
    const float* Wk = (const float*)d_in[5];
    const float* Wv = (const float*)d_in[7];
    const float* bv = (const float*)d_in[8];
    const float* Wo = (const float*)d_in[9];
    const float* bo = (const float*)d_in[10];
    float* out = (float*)d_out;

    float *Vp, *pre, *Wvr, *Wor, *qm, *km, *Wm, *w;
    int* delays;
    cudaGetSymbolAddress((void**)&Vp, g_Vp);
    cudaGetSymbolAddress((void**)&pre, g_pre);
    cudaGetSymbolAddress((void**)&Wvr, g_Wvr);
    cudaGetSymbolAddress((void**)&Wor, g_Wor);
    cudaGetSymbolAddress((void**)&qm, g_qm);
    cudaGetSymbolAddress((void**)&km, g_km);
    cudaGetSymbolAddress((void**)&Wm, g_Wm);
    cudaGetSymbolAddress((void**)&w, g_w);
    cudaGetSymbolAddress((void**)&delays, g_delays);

    cudaFuncSetAttribute(gemm_tf32_kernel<true>,
                         cudaFuncAttributeMaxDynamicSharedMemorySize, GEMM_SMEM);
    cudaFuncSetAttribute(gemm_tf32_kernel<false>,
                         cudaFuncAttributeMaxDynamicSharedMemorySize, GEMM_SMEM);
    cudaFuncSetAttribute(qkmean_kernel,
                         cudaFuncAttributeMaxDynamicSharedMemorySize, 131072);
    cudaFuncSetAttribute(fft_corr_top8_kernel,
                         cudaFuncAttributeMaxDynamicSharedMemorySize, 81920);

    dim3 gemm_grid(4, 128);   // 512 blocks, 128x256 tiles

    // fork-join: side chain depends only on inputs
    cudaStream_t side;
    cudaEvent_t evFork, evJoin;
    cudaStreamCreateWithFlags(&side, cudaStreamNonBlocking);
    cudaEventCreateWithFlags(&evFork, cudaEventDisableTiming);
    cudaEventCreateWithFlags(&evJoin, cudaEventDisableTiming);

    cudaEventRecord(evFork, 0);
    cudaStreamWaitEvent(side, evFork, 0);

    // main stream: V projection (critical path)
    wprep_kernel<<<4096, 256>>>(Wv, Wvr);
    gemm_tf32_kernel<true><<<gemm_grid, 256, GEMM_SMEM>>>(values, Wvr, bv, Vp);

    // side stream: mean path + Wo prep (hidden under V-GEMM)
    wprep_kernel<<<4096, 256, 0, side>>>(Wo, Wor);
    wmean_kernel<<<128, 256, 0, side>>>(Wq, Wk, Wm);
    qkmean_kernel<<<512, 256, 131072, side>>>(queries, keys, Wm, qm, km);
    fft_corr_top8_kernel<<<BH_, 512, 81920, side>>>(qm, km, w, delays);
    cudaEventRecord(evJoin, side);

    // join, then gather + output projection
    cudaStreamWaitEvent(0, evJoin, 0);
    gather_kernel<<<(M_ * D_ / 4) / 256, 256>>>(Vp, w, delays, pre);
    gemm_tf32_kernel<false><<<gemm_grid, 256, GEMM_SMEM>>>(pre, Wor, bo, out);
}